// round 12
// baseline (speedup 1.0000x reference)
#include <cuda_runtime.h>
#include <cuda_fp16.h>
#include <math.h>
#include <stdint.h>

#define NB 16
#define NC 96
#define NR 4
#define NO 48
#define NH 66
#define NHW (NH*NH)          // 4356
#define NCR (NC*NR)          // 384
#define BN_EPS 2e-5f
#define NPIX_PER_CH (NB*NR*NHW)

// ---- conv GEMM config ----
#define CHC 16                          // channels per chunk
#define NCHUNK 24                       // 384/16
#define WB_PER_CHUNK (9*6*32)           // 1728 u64
#define WB_TOTAL (NR*NCHUNK*WB_PER_CHUNK)
#define ROWS 4
#define IR (ROWS+2)
#define IPX (IR*66)                     // 396
#define ABUF_BYTES (IPX*32)             // 12672  (fp16 only, no lo term)
#define CONV_DYN (1024 + 2*ABUF_BYTES + 2*WB_PER_CHUNK*8)   // 54016

// ---------------- scratch (device globals) ----------------
__device__ float d_psum[NC*8];
__device__ float d_psq[NC*8];
__device__ float d_savg[NB*NCR];
__device__ float d_smax[NB*NCR];
__device__ float d_ca[NB*NR*NCR];
__device__ float d_um[NB*NR*NHW];
__device__ float d_ux[NB*NR*NHW];
__device__ float d_sp[NB*NR*NHW];
__device__ float d_wsa[NR*2*NR*49];
__device__ unsigned long long d_wb[WB_TOTAL];

__device__ __forceinline__ uint32_t smem_u32(const void* p) {
    uint32_t a;
    asm("{ .reg .u64 t; cvta.to.shared.u64 t, %1; cvt.u32.u64 %0, t; }" : "=r"(a) : "l"(p));
    return a;
}
__device__ __forceinline__ float warpSum(float v) {
    #pragma unroll
    for (int o = 16; o; o >>= 1) v += __shfl_down_sync(0xffffffffu, v, o);
    return v;
}
__device__ __forceinline__ float warpMax(float v) {
    #pragma unroll
    for (int o = 16; o; o >>= 1) v = fmaxf(v, __shfl_down_sync(0xffffffffu, v, o));
    return v;
}
__device__ __forceinline__ float sigmoidf(float v) { return 1.f / (1.f + expf(-v)); }

#define LDSM_X4(r0, r1, r2, r3, addr) \
    asm volatile("ldmatrix.sync.aligned.m8n8.x4.shared.b16 {%0,%1,%2,%3}, [%4];" \
        : "=r"(r0), "=r"(r1), "=r"(r2), "=r"(r3) : "r"(addr))

#define MMA16816F16(c, a0, a1, a2, a3, b0, b1) \
    asm volatile("mma.sync.aligned.m16n8k16.row.col.f32.f16.f16.f32 " \
        "{%0,%1,%2,%3}, {%4,%5,%6,%7}, {%8,%9}, {%0,%1,%2,%3};" \
        : "+f"((c)[0]), "+f"((c)[1]), "+f"((c)[2]), "+f"((c)[3]) \
        : "r"(a0), "r"(a1), "r"(a2), "r"(a3), "r"(b0), "r"(b1))

__device__ __forceinline__ void bn_affine(int c, const float* gamma, const float* beta,
                                          float& ga, float& gb) {
    float s = 0.f, q = 0.f;
    #pragma unroll
    for (int j = 0; j < 8; j++) { s += d_psum[c*8+j]; q += d_psq[c*8+j]; }
    float mean = s * (1.f / NPIX_PER_CH);
    float var  = q * (1.f / NPIX_PER_CH) - mean*mean;
    ga = gamma[c] * rsqrtf(var + BN_EPS);
    gb = beta[c] - mean * ga;
}

// ---------------- L0: stats + SA weights + fp16 B prepack ----------------
__global__ void k_init(const float* __restrict__ x, const float* __restrict__ cw,
                       const float* __restrict__ sw) {
    int bx = blockIdx.x, tid = threadIdx.x;
    if (bx < 768) {
        int c = bx >> 3, part = bx & 7;
        float s = 0.f, q = 0.f;
        #pragma unroll
        for (int b2 = 0; b2 < 2; b2++) {
            const float4* p4 = (const float4*)(x + (size_t)((part*2 + b2)*NC + c) * (NR*NHW));
            for (int i = tid; i < NR*NHW/4; i += 256) {
                float4 v = p4[i];
                s += v.x + v.y + v.z + v.w;
                q += v.x*v.x + v.y*v.y + v.z*v.z + v.w*v.w;
            }
        }
        __shared__ float rs[8], rq[8];
        int wid = tid >> 5, lane = tid & 31;
        s = warpSum(s); q = warpSum(q);
        if (lane == 0) { rs[wid] = s; rq[wid] = q; }
        __syncthreads();
        if (tid == 0) {
            float S = 0.f, Q = 0.f;
            #pragma unroll
            for (int j = 0; j < 8; j++) { S += rs[j]; Q += rq[j]; }
            d_psum[c*8 + part] = S;
            d_psq [c*8 + part] = Q;
        }
    } else if (bx < 775) {
        int idx = (bx - 768)*256 + tid;
        if (idx >= NR*2*NR*49) return;
        int ij = idx % 49; int t = idx / 49;
        int r  = t & 3;    t >>= 2;
        int p  = t & 1;    int h = t >> 1;
        int i = ij / 7, j = ij % 7;
        int rs = (r - h) & 3;
        int si, sj;
        switch (h) {
            case 0:  si = i;     sj = j;     break;
            case 1:  si = j;     sj = 6 - i; break;
            case 2:  si = 6 - i; sj = 6 - j; break;
            default: si = 6 - j; sj = i;     break;
        }
        d_wsa[idx] = sw[(p*NR + rs)*49 + si*7 + sj];
    } else {
        int idx = (bx - 775)*256 + tid;
        if (idx >= WB_TOTAL) return;
        int lane = idx & 31; int t = idx >> 5;
        int nt   = t % 6;    t /= 6;
        int tap  = t % 9;    t /= 9;
        int chunk = t % NCHUNK;
        int h = t / NCHUNK;
        int n = nt*8 + (lane >> 2);
        int k0 = (lane & 3)*2;
        int i = tap / 3, j = tap % 3, si, sj;
        switch (h) {
            case 0:  si = i;     sj = j;     break;
            case 1:  si = j;     sj = 2 - i; break;
            case 2:  si = 2 - i; sj = 2 - j; break;
            default: si = 2 - j; sj = i;     break;
        }
        unsigned long long pk = 0;
        #pragma unroll
        for (int q = 0; q < 4; q++) {
            int kk = k0 + (q & 1) + (q >> 1)*8;
            int cr = chunk*CHC + kk;
            int c = cr >> 2, r = cr & 3;
            int rs = (r - h) & 3;
            float w = cw[(((n*NC + c)*NR + rs)*3 + si)*3 + sj];
            unsigned short bits = __half_as_ushort(__float2half(w));
            pk |= (unsigned long long)bits << (q*16);
        }
        d_wb[idx] = pk;
    }
}

// ---------------- L1: spatial squeeze + channel pooling ----------------
#define PB 18
__global__ void k_pool(const float* __restrict__ x, const float* __restrict__ gamma,
                       const float* __restrict__ beta) {
    int bx = blockIdx.x, tid = threadIdx.x;
    if (bx < NB*NCR) {
        int id = bx;
        int c = (id >> 2) % NC;
        float ga, gb;
        bn_affine(c, gamma, beta, ga, gb);
        const float* p = x + (size_t)id * NHW;
        float s = 0.f, m = 0.f;
        for (int i = tid; i < NHW; i += 256) {
            float v = fmaxf(fmaf(ga, p[i], gb), 0.f);
            s += v; m = fmaxf(m, v);
        }
        __shared__ float rs[8], rm[8];
        int wid = tid >> 5, lane = tid & 31;
        s = warpSum(s); m = warpMax(m);
        if (lane == 0) { rs[wid] = s; rm[wid] = m; }
        __syncthreads();
        if (tid == 0) {
            float S = 0.f, M = 0.f;
            #pragma unroll
            for (int j = 0; j < 8; j++) { S += rs[j]; M = fmaxf(M, rm[j]); }
            d_savg[id] = S * (1.f / NHW);
            d_smax[id] = M;
        }
    } else {
        __shared__ float sga[NC], sgb[NC];
        if (tid < NC) bn_affine(tid, gamma, beta, sga[tid], sgb[tid]);
        __syncthreads();
        int idx = bx - NB*NCR;
        int pb = idx % PB, br = idx / PB;
        int b = br >> 2, r = br & 3;
        int p = pb*256 + tid;
        if (p >= NHW) return;
        float s = 0.f, m = 0.f;
        const float* xb = x + (size_t)(b*NCR + r) * NHW + p;
        #pragma unroll 4
        for (int c = 0; c < NC; c++) {
            float v = fmaxf(fmaf(sga[c], xb[(size_t)(c*4) * NHW], sgb[c]), 0.f);
            s += v; m = fmaxf(m, v);
        }
        d_um[br*NHW + p] = s * (1.f / NC);
        d_ux[br*NHW + p] = m;
    }
}

// ---------------- L2: merged channel-attention MLP + spatial attention ------------
__global__ void k_att(const float* __restrict__ fc1, const float* __restrict__ fc2) {
    int bx = blockIdx.x, tid = threadIdx.x;
    if (bx < NB) {
        int b = bx;
        __shared__ float sA[NCR], sM[NCR], f1[2*NCR], f2[NC*8];
        __shared__ float dred[16], hsum[8];
        for (int i = tid; i < NCR; i += 256) { sA[i] = d_savg[b*NCR + i]; sM[i] = d_smax[b*NCR + i]; }
        for (int i = tid; i < 2*NCR; i += 256) { f1[i] = fc1[i]; f2[i] = fc2[i]; }
        __syncthreads();
        int wid = tid >> 5, lane = tid & 31;
        #pragma unroll
        for (int dd = 0; dd < 2; dd++) {
            int d = wid*2 + dd;
            int sel = d & 1, he = d >> 1;
            int h = he >> 1, e = he & 1;
            const float* sv = sel ? sM : sA;
            float sum = 0.f;
            for (int k = lane; k < NCR; k += 32) {
                int r = k & 3;
                sum += sv[k] * f1[e*NCR + (k & ~3) + (((r - h) & 3))];
            }
            sum = warpSum(sum);
            if (lane == 0) dred[d] = fmaxf(sum, 0.f);
        }
        __syncthreads();
        if (tid < 8) hsum[tid] = dred[tid*2] + dred[tid*2 + 1];
        __syncthreads();
        for (int idx = tid; idx < NR*NCR; idx += 256) {
            int h = idx / NCR, cr = idx % NCR;
            int c = cr >> 2, r = cr & 3;
            int rs = (r - h) & 3;
            float v = hsum[h*2 + 0] * f2[c*8 + rs]
                    + hsum[h*2 + 1] * f2[c*8 + 4 + rs];
            d_ca[b*(NR*NCR) + idx] = sigmoidf(v);
        }
    } else {
        __shared__ float ws[2*NR*49];
        int idx = bx - NB;
        int pb = idx % PB, bh = idx / PB;
        int b = bh >> 2, h = bh & 3;
        for (int i = tid; i < 2*NR*49; i += 256) ws[i] = d_wsa[h*(2*NR*49) + i];
        __syncthreads();
        int p = pb*256 + tid;
        if (p >= NHW) return;
        int y = p / NH, x0 = p % NH;
        float s = 0.f;
        #pragma unroll
        for (int p2 = 0; p2 < 2; p2++) {
            const float* ubase = p2 ? d_ux : d_um;
            #pragma unroll
            for (int r = 0; r < NR; r++) {
                const float* u = ubase + (size_t)(b*4 + r) * NHW;
                const float* w = ws + (p2*4 + r)*49;
                #pragma unroll
                for (int i = 0; i < 7; i++) {
                    int Y = y + i - 3;
                    if (Y < 0 || Y >= NH) continue;
                    #pragma unroll
                    for (int j = 0; j < 7; j++) {
                        int X = x0 + j - 3;
                        if (X < 0 || X >= NH) continue;
                        s += u[Y*NH + X] * w[i*7 + j];
                    }
                }
            }
        }
        d_sp[bh*NHW + p] = sigmoidf(s);
    }
}

// ---------------- L3 (PROFILED): double-buffered plain-fp16 HMMA conv -------------
// A tile: 32B per input pixel = 2x16B units [k0-7][k8-15] fp16;
// swizzle off ^= (off>>3)&0x10 -> conflict-free LDSM + STS.128.
__global__ __launch_bounds__(256, 2) void k_conv(const float* __restrict__ x,
                                                 const float* __restrict__ gamma,
                                                 const float* __restrict__ beta,
                                                 float* __restrict__ out) {
    extern __shared__ __align__(16) char dyn[];
    __shared__ float s_sp[IPX];
    __shared__ float s_ga[NCR], s_gb[NCR];
    __shared__ float s_gac[NC], s_gbc[NC];

    char* sbase;
    { uintptr_t p0 = (uintptr_t)dyn; p0 = (p0 + 1023) & ~(uintptr_t)1023; sbase = (char*)p0; }
    char* sAc = sbase;                                            // [2][ABUF_BYTES]
    unsigned long long* sBb = (unsigned long long*)(sbase + 2*ABUF_BYTES);  // [2][1728]
    uint4* sB4 = (uint4*)sBb;

    int ytile = blockIdx.x, bh = blockIdx.y;
    int b = bh >> 2, h = bh & 3;
    int y0 = ytile * ROWS;
    int tid = threadIdx.x, lane = tid & 31, w = tid >> 5;

    if (tid < NC) bn_affine(tid, gamma, beta, s_gac[tid], s_gbc[tid]);
    for (int i = tid; i < IPX; i += 256) {
        int row = i / 66, col = i - row*66;
        s_sp[i] = d_sp[bh*NHW + (y0 + row)*NH + col];
    }
    __syncthreads();
    for (int i = tid; i < NCR; i += 256) {
        float ca = d_ca[bh*NCR + i];
        int c = i >> 2;
        s_ga[i] = s_gac[c] * ca;
        s_gb[i] = s_gbc[c] * ca;
    }

    float acc[2][6][4];
    #pragma unroll
    for (int t = 0; t < 2; t++)
        #pragma unroll
        for (int nt = 0; nt < 6; nt++)
            #pragma unroll
            for (int q = 0; q < 4; q++) acc[t][nt][q] = 0.f;

    // fragment geometry
    int matrix = lane >> 3, mrow = lane & 7;
    int fragrow = ((matrix & 1) << 3) + mrow;
    int colhalf = matrix >> 1;
    uint32_t sA_u32 = smem_u32(sAc);
    uint32_t pxoff[2];
    #pragma unroll
    for (int t = 0; t < 2; t++) {
        int tt = 2*w + t;
        int pxb = (tt >> 2)*66 + (tt & 3)*16 + fragrow;
        pxoff[t] = (uint32_t)(pxb*32 + colhalf*16);
    }

    const float* xb = x + (size_t)b * NCR * NHW;
    const uint4* wbsrc = (const uint4*)(d_wb) + (size_t)h * NCHUNK * 864;

    // ---- prologue: build chunk 0 into buffer 0 ----
    for (int i = tid; i < 864; i += 256) sB4[i] = wbsrc[i];
    for (int s = tid; s < 2*IPX; s += 256) {
        int hh = s / IPX, p = s - hh*IPX;
        int row = p / 66, col = p - row*66;
        const float* xp = xb + (size_t)(hh*8) * NHW + (y0 + row)*NH + col;
        float sp = s_sp[p];
        uint32_t wv[4];
        #pragma unroll
        for (int j = 0; j < 4; j++) {
            int cra = hh*8 + 2*j;
            float v0 = fmaxf(fmaf(s_ga[cra],     xp[(size_t)(2*j)*NHW],     s_gb[cra]),     0.f) * sp;
            float v1 = fmaxf(fmaf(s_ga[cra + 1], xp[(size_t)(2*j + 1)*NHW], s_gb[cra + 1]), 0.f) * sp;
            __half h0 = __float2half(v0), h1 = __float2half(v1);
            wv[j] = (uint32_t)__half_as_ushort(h0) | ((uint32_t)__half_as_ushort(h1) << 16);
        }
        uint32_t off = (uint32_t)(p*32 + hh*16); off ^= (off >> 3) & 0x10;
        *(uint4*)(sAc + off) = make_uint4(wv[0], wv[1], wv[2], wv[3]);
    }
    __syncthreads();

    // ---- main pipeline ----
    for (int chunk = 0; chunk < NCHUNK; chunk++) {
        int cb = chunk & 1, nb = cb ^ 1;
        int nk = (chunk + 1 < NCHUNK) ? chunk + 1 : 0;
        int ncr0 = nk * CHC;

        // (1) prefetch next A floats into registers
        float va[4][8];
        #pragma unroll
        for (int g = 0; g < 4; g++) {
            int s = tid + g*256;
            if (s < 2*IPX) {
                int hh = s / IPX, p = s - hh*IPX;
                int row = p / 66, col = p - row*66;
                const float* xp = xb + (size_t)(ncr0 + hh*8) * NHW + (y0 + row)*NH + col;
                #pragma unroll
                for (int j = 0; j < 8; j++) va[g][j] = xp[(size_t)j * NHW];
            }
        }

        // (2) MMA taps on current buffer
        uint32_t abase = sA_u32 + (uint32_t)cb * ABUF_BYTES;
        const unsigned long long* bcur = sBb + cb*1728 + lane;
        #pragma unroll
        for (int tap = 0; tap < 9; tap++) {
            const int d = (tap/3)*66 + (tap%3);
            uint32_t o0 = pxoff[0] + (uint32_t)(d*32); o0 ^= (o0 >> 3) & 0x10;
            uint32_t o1 = pxoff[1] + (uint32_t)(d*32); o1 ^= (o1 >> 3) & 0x10;
            uint32_t a0 = abase + o0, a1 = abase + o1;
            uint32_t h00, h01, h02, h03, h10, h11, h12, h13;
            LDSM_X4(h00, h01, h02, h03, a0);
            LDSM_X4(h10, h11, h12, h13, a1);
            const unsigned long long* bp = bcur + tap*192;
            #pragma unroll
            for (int nt = 0; nt < 6; nt++) {
                unsigned long long b2 = bp[nt*32];
                uint32_t b0 = (uint32_t)b2, b1 = (uint32_t)(b2 >> 32);
                MMA16816F16(acc[0][nt], h00, h01, h02, h03, b0, b1);
                MMA16816F16(acc[1][nt], h10, h11, h12, h13, b0, b1);
            }
        }

        // (3) copy next B into other buffer (L2-hot)
        {
            const uint4* bs = wbsrc + (size_t)nk * 864;
            uint4* bd = sB4 + nb*864;
            #pragma unroll
            for (int i = tid; i < 864; i += 256) bd[i] = bs[i];
        }

        // (4) convert prefetched A -> swizzled STS into other buffer
        #pragma unroll
        for (int g = 0; g < 4; g++) {
            int s = tid + g*256;
            if (s < 2*IPX) {
                int hh = s / IPX, p = s - hh*IPX;
                float sp = s_sp[p];
                uint32_t wv[4];
                #pragma unroll
                for (int j = 0; j < 4; j++) {
                    int cra = ncr0 + hh*8 + 2*j;
                    float v0 = fmaxf(fmaf(s_ga[cra],     va[g][2*j],     s_gb[cra]),     0.f) * sp;
                    float v1 = fmaxf(fmaf(s_ga[cra + 1], va[g][2*j + 1], s_gb[cra + 1]), 0.f) * sp;
                    __half h0 = __float2half(v0), h1 = __float2half(v1);
                    wv[j] = (uint32_t)__half_as_ushort(h0) | ((uint32_t)__half_as_ushort(h1) << 16);
                }
                uint32_t off = (uint32_t)(p*32 + hh*16); off ^= (off >> 3) & 0x10;
                *(uint4*)(sAc + (size_t)nb * ABUF_BYTES + off) = make_uint4(wv[0], wv[1], wv[2], wv[3]);
            }
        }
        __syncthreads();
    }

    // epilogue
    #pragma unroll
    for (int t = 0; t < 2; t++) {
        int tt = 2*w + t;
        int ox = (tt & 3)*16 + (lane >> 2);
        int oy = y0 + (tt >> 2);
        #pragma unroll
        for (int nt = 0; nt < 6; nt++) {
            int o0 = nt*8 + (lane & 3)*2;
            size_t i0 = (((size_t)(b*144 + o0))*4 + h)*4096 + (size_t)oy*64;
            out[i0 + ox]               = acc[t][nt][0];
            out[i0 + 16384 + ox]       = acc[t][nt][1];
            out[i0 + ox + 8]           = acc[t][nt][2];
            out[i0 + 16384 + ox + 8]   = acc[t][nt][3];
        }
    }
}

// ---------------- L4: dense concat crop ----------------
__global__ void k_crop(const float* __restrict__ x, float* __restrict__ out) {
    int idx = blockIdx.x*256 + threadIdx.x;
    if (idx >= NB*NC*NR*64*16) return;
    int q   = idx & 15;
    int y   = (idx >> 4) & 63;
    int brc = idx >> 10;
    int b   = brc / NCR;
    int crr = brc % NCR;
    int c   = crr >> 2, r = crr & 3;
    const float* src = x + (size_t)brc * NHW + (size_t)(y + 1)*NH + (q*4 + 1);
    float4 v = make_float4(src[0], src[1], src[2], src[3]);
    size_t off = (((size_t)b*144 + 48 + c)*4 + r)*4096 + (size_t)y*64 + q*4;
    *(float4*)(out + off) = v;
}

// ---------------- launch ----------------
extern "C" void kernel_launch(void* const* d_in, const int* in_sizes, int n_in,
                              void* d_out, int out_size) {
    const float* x     = (const float*)d_in[0];
    const float* gamma = (const float*)d_in[1];
    const float* beta  = (const float*)d_in[2];
    const float* fc1   = (const float*)d_in[3];
    const float* fc2   = (const float*)d_in[4];
    const float* sa    = (const float*)d_in[5];
    const float* cw    = (const float*)d_in[6];
    float* out = (float*)d_out;
    (void)in_sizes; (void)n_in; (void)out_size;

    static int smem_set = 0;
    if (!smem_set) {
        cudaFuncSetAttribute(k_conv, cudaFuncAttributeMaxDynamicSharedMemorySize, CONV_DYN);
        smem_set = 1;
    }

    int init_blocks = 775 + (WB_TOTAL + 255)/256;
    k_init<<<init_blocks, 256>>>(x, cw, sa);                       // 0
    k_pool<<<NB*NCR + PB*NB*NR, 256>>>(x, gamma, beta);            // 1
    k_att <<<NB + PB*NB*NR, 256>>>(fc1, fc2);                      // 2
    k_conv<<<dim3(16, NB*NR), 256, CONV_DYN>>>(x, gamma, beta, out);  // 3  <- profiled
    k_crop<<<(NB*NC*NR*64*16 + 255)/256, 256>>>(x, out);           // 4
}

// round 14
// speedup vs baseline: 1.3021x; 1.3021x over previous
#include <cuda_runtime.h>
#include <cuda_fp16.h>
#include <math.h>
#include <stdint.h>

#define NB 16
#define NC 96
#define NR 4
#define NO 48
#define NH 66
#define NHW (NH*NH)          // 4356
#define NCR (NC*NR)          // 384
#define BN_EPS 2e-5f
#define NPIX_PER_CH (NB*NR*NHW)

// ---- conv GEMM config ----
#define CHC 16                          // channels per chunk
#define NCHUNK 24                       // 384/16
#define WB_PER_CHUNK (9*6*32)           // 1728 u64
#define WB_TOTAL (NR*NCHUNK*WB_PER_CHUNK)
#define BBUF_BYTES (WB_PER_CHUNK*8)     // 13824
#define ROWS 8                          // output rows per block
#define IR (ROWS+2)                     // 10
#define IPX (IR*66)                     // 660
#define ABUF_BYTES (IPX*32)             // 21120 (fp16, 32B/px)
#define CONV_DYN (1024 + 2*ABUF_BYTES + 2*BBUF_BYTES)   // 70912

// ---------------- scratch (device globals) ----------------
__device__ float d_psum[NC*8];
__device__ float d_psq[NC*8];
__device__ float d_savg[NB*NCR];
__device__ float d_smax[NB*NCR];
__device__ float d_ca[NB*NR*NCR];
__device__ float d_um[NB*NR*NHW];
__device__ float d_ux[NB*NR*NHW];
__device__ float d_sp[NB*NR*NHW];
__device__ float d_wsa[NR*2*NR*49];
__device__ unsigned long long d_wb[WB_TOTAL];

__device__ __forceinline__ uint32_t smem_u32(const void* p) {
    uint32_t a;
    asm("{ .reg .u64 t; cvta.to.shared.u64 t, %1; cvt.u32.u64 %0, t; }" : "=r"(a) : "l"(p));
    return a;
}
__device__ __forceinline__ float warpSum(float v) {
    #pragma unroll
    for (int o = 16; o; o >>= 1) v += __shfl_down_sync(0xffffffffu, v, o);
    return v;
}
__device__ __forceinline__ float warpMax(float v) {
    #pragma unroll
    for (int o = 16; o; o >>= 1) v = fmaxf(v, __shfl_down_sync(0xffffffffu, v, o));
    return v;
}
__device__ __forceinline__ float sigmoidf(float v) { return 1.f / (1.f + expf(-v)); }

#define LDSM_X4(r0, r1, r2, r3, addr) \
    asm volatile("ldmatrix.sync.aligned.m8n8.x4.shared.b16 {%0,%1,%2,%3}, [%4];" \
        : "=r"(r0), "=r"(r1), "=r"(r2), "=r"(r3) : "r"(addr))

#define MMA16816F16(c, a0, a1, a2, a3, b0, b1) \
    asm volatile("mma.sync.aligned.m16n8k16.row.col.f32.f16.f16.f32 " \
        "{%0,%1,%2,%3}, {%4,%5,%6,%7}, {%8,%9}, {%0,%1,%2,%3};" \
        : "+f"((c)[0]), "+f"((c)[1]), "+f"((c)[2]), "+f"((c)[3]) \
        : "r"(a0), "r"(a1), "r"(a2), "r"(a3), "r"(b0), "r"(b1))

#define CP_ASYNC16(dst, src) \
    asm volatile("cp.async.cg.shared.global [%0], [%1], 16;" :: "r"(dst), "l"(src) : "memory")
#define CP_ASYNC_COMMIT() asm volatile("cp.async.commit_group;" ::: "memory")
#define CP_ASYNC_WAIT0()  asm volatile("cp.async.wait_group 0;" ::: "memory")

__device__ __forceinline__ void bn_affine(int c, const float* gamma, const float* beta,
                                          float& ga, float& gb) {
    float s = 0.f, q = 0.f;
    #pragma unroll
    for (int j = 0; j < 8; j++) { s += d_psum[c*8+j]; q += d_psq[c*8+j]; }
    float mean = s * (1.f / NPIX_PER_CH);
    float var  = q * (1.f / NPIX_PER_CH) - mean*mean;
    ga = gamma[c] * rsqrtf(var + BN_EPS);
    gb = beta[c] - mean * ga;
}

// ---------------- L0: stats + SA weights + fp16 B prepack ----------------
__global__ void k_init(const float* __restrict__ x, const float* __restrict__ cw,
                       const float* __restrict__ sw) {
    int bx = blockIdx.x, tid = threadIdx.x;
    if (bx < 768) {
        int c = bx >> 3, part = bx & 7;
        float s = 0.f, q = 0.f;
        #pragma unroll
        for (int b2 = 0; b2 < 2; b2++) {
            const float4* p4 = (const float4*)(x + (size_t)((part*2 + b2)*NC + c) * (NR*NHW));
            for (int i = tid; i < NR*NHW/4; i += 256) {
                float4 v = p4[i];
                s += v.x + v.y + v.z + v.w;
                q += v.x*v.x + v.y*v.y + v.z*v.z + v.w*v.w;
            }
        }
        __shared__ float rs[8], rq[8];
        int wid = tid >> 5, lane = tid & 31;
        s = warpSum(s); q = warpSum(q);
        if (lane == 0) { rs[wid] = s; rq[wid] = q; }
        __syncthreads();
        if (tid == 0) {
            float S = 0.f, Q = 0.f;
            #pragma unroll
            for (int j = 0; j < 8; j++) { S += rs[j]; Q += rq[j]; }
            d_psum[c*8 + part] = S;
            d_psq [c*8 + part] = Q;
        }
    } else if (bx < 775) {
        int idx = (bx - 768)*256 + tid;
        if (idx >= NR*2*NR*49) return;
        int ij = idx % 49; int t = idx / 49;
        int r  = t & 3;    t >>= 2;
        int p  = t & 1;    int h = t >> 1;
        int i = ij / 7, j = ij % 7;
        int rs = (r - h) & 3;
        int si, sj;
        switch (h) {
            case 0:  si = i;     sj = j;     break;
            case 1:  si = j;     sj = 6 - i; break;
            case 2:  si = 6 - i; sj = 6 - j; break;
            default: si = 6 - j; sj = i;     break;
        }
        d_wsa[idx] = sw[(p*NR + rs)*49 + si*7 + sj];
    } else {
        int idx = (bx - 775)*256 + tid;
        if (idx >= WB_TOTAL) return;
        int lane = idx & 31; int t = idx >> 5;
        int nt   = t % 6;    t /= 6;
        int tap  = t % 9;    t /= 9;
        int chunk = t % NCHUNK;
        int h = t / NCHUNK;
        int n = nt*8 + (lane >> 2);
        int k0 = (lane & 3)*2;
        int i = tap / 3, j = tap % 3, si, sj;
        switch (h) {
            case 0:  si = i;     sj = j;     break;
            case 1:  si = j;     sj = 2 - i; break;
            case 2:  si = 2 - i; sj = 2 - j; break;
            default: si = 2 - j; sj = i;     break;
        }
        unsigned long long pk = 0;
        #pragma unroll
        for (int q = 0; q < 4; q++) {
            int kk = k0 + (q & 1) + (q >> 1)*8;
            int cr = chunk*CHC + kk;
            int c = cr >> 2, r = cr & 3;
            int rs = (r - h) & 3;
            float w = cw[(((n*NC + c)*NR + rs)*3 + si)*3 + sj];
            unsigned short bits = __half_as_ushort(__float2half(w));
            pk |= (unsigned long long)bits << (q*16);
        }
        d_wb[idx] = pk;
    }
}

// ---------------- L1: spatial squeeze + channel pooling ----------------
#define PB 18
__global__ void k_pool(const float* __restrict__ x, const float* __restrict__ gamma,
                       const float* __restrict__ beta) {
    int bx = blockIdx.x, tid = threadIdx.x;
    if (bx < NB*NCR) {
        int id = bx;
        int c = (id >> 2) % NC;
        float ga, gb;
        bn_affine(c, gamma, beta, ga, gb);
        const float* p = x + (size_t)id * NHW;
        float s = 0.f, m = 0.f;
        for (int i = tid; i < NHW; i += 256) {
            float v = fmaxf(fmaf(ga, p[i], gb), 0.f);
            s += v; m = fmaxf(m, v);
        }
        __shared__ float rs[8], rm[8];
        int wid = tid >> 5, lane = tid & 31;
        s = warpSum(s); m = warpMax(m);
        if (lane == 0) { rs[wid] = s; rm[wid] = m; }
        __syncthreads();
        if (tid == 0) {
            float S = 0.f, M = 0.f;
            #pragma unroll
            for (int j = 0; j < 8; j++) { S += rs[j]; M = fmaxf(M, rm[j]); }
            d_savg[id] = S * (1.f / NHW);
            d_smax[id] = M;
        }
    } else {
        __shared__ float sga[NC], sgb[NC];
        if (tid < NC) bn_affine(tid, gamma, beta, sga[tid], sgb[tid]);
        __syncthreads();
        int idx = bx - NB*NCR;
        int pb = idx % PB, br = idx / PB;
        int b = br >> 2, r = br & 3;
        int p = pb*256 + tid;
        if (p >= NHW) return;
        float s = 0.f, m = 0.f;
        const float* xb = x + (size_t)(b*NCR + r) * NHW + p;
        #pragma unroll 4
        for (int c = 0; c < NC; c++) {
            float v = fmaxf(fmaf(sga[c], xb[(size_t)(c*4) * NHW], sgb[c]), 0.f);
            s += v; m = fmaxf(m, v);
        }
        d_um[br*NHW + p] = s * (1.f / NC);
        d_ux[br*NHW + p] = m;
    }
}

// ---------------- L2: merged channel-attention MLP + spatial attention ------------
__global__ void k_att(const float* __restrict__ fc1, const float* __restrict__ fc2) {
    int bx = blockIdx.x, tid = threadIdx.x;
    if (bx < NB) {
        int b = bx;
        __shared__ float sA[NCR], sM[NCR], f1[2*NCR], f2[NC*8];
        __shared__ float dred[16], hsum[8];
        for (int i = tid; i < NCR; i += 256) { sA[i] = d_savg[b*NCR + i]; sM[i] = d_smax[b*NCR + i]; }
        for (int i = tid; i < 2*NCR; i += 256) { f1[i] = fc1[i]; f2[i] = fc2[i]; }
        __syncthreads();
        int wid = tid >> 5, lane = tid & 31;
        #pragma unroll
        for (int dd = 0; dd < 2; dd++) {
            int d = wid*2 + dd;
            int sel = d & 1, he = d >> 1;
            int h = he >> 1, e = he & 1;
            const float* sv = sel ? sM : sA;
            float sum = 0.f;
            for (int k = lane; k < NCR; k += 32) {
                int r = k & 3;
                sum += sv[k] * f1[e*NCR + (k & ~3) + (((r - h) & 3))];
            }
            sum = warpSum(sum);
            if (lane == 0) dred[d] = fmaxf(sum, 0.f);
        }
        __syncthreads();
        if (tid < 8) hsum[tid] = dred[tid*2] + dred[tid*2 + 1];
        __syncthreads();
        for (int idx = tid; idx < NR*NCR; idx += 256) {
            int h = idx / NCR, cr = idx % NCR;
            int c = cr >> 2, r = cr & 3;
            int rs = (r - h) & 3;
            float v = hsum[h*2 + 0] * f2[c*8 + rs]
                    + hsum[h*2 + 1] * f2[c*8 + 4 + rs];
            d_ca[b*(NR*NCR) + idx] = sigmoidf(v);
        }
    } else {
        __shared__ float ws[2*NR*49];
        int idx = bx - NB;
        int pb = idx % PB, bh = idx / PB;
        int b = bh >> 2, h = bh & 3;
        for (int i = tid; i < 2*NR*49; i += 256) ws[i] = d_wsa[h*(2*NR*49) + i];
        __syncthreads();
        int p = pb*256 + tid;
        if (p >= NHW) return;
        int y = p / NH, x0 = p % NH;
        float s = 0.f;
        #pragma unroll
        for (int p2 = 0; p2 < 2; p2++) {
            const float* ubase = p2 ? d_ux : d_um;
            #pragma unroll
            for (int r = 0; r < NR; r++) {
                const float* u = ubase + (size_t)(b*4 + r) * NHW;
                const float* w = ws + (p2*4 + r)*49;
                #pragma unroll
                for (int i = 0; i < 7; i++) {
                    int Y = y + i - 3;
                    if (Y < 0 || Y >= NH) continue;
                    #pragma unroll
                    for (int j = 0; j < 7; j++) {
                        int X = x0 + j - 3;
                        if (X < 0 || X >= NH) continue;
                        s += u[Y*NH + X] * w[i*7 + j];
                    }
                }
            }
        }
        d_sp[bh*NHW + p] = sigmoidf(s);
    }
}

// ---------------- L3 (PROFILED): fp16 HMMA conv, 4 m-tiles/warp, cp.async B -------
// Block: 256 thr = 8 warps; 8 output rows x 64 px (M=512); warp w owns output row w
// (4 m16 tiles). A: 32B/px, swizzle off ^= (off>>3)&0x10.
// FIX vs R13: __syncthreads() between s_ga/s_gb fill and first A-build (race).
__global__ __launch_bounds__(256, 2) void k_conv(const float* __restrict__ x,
                                                 const float* __restrict__ gamma,
                                                 const float* __restrict__ beta,
                                                 float* __restrict__ out) {
    extern __shared__ __align__(16) char dyn[];
    __shared__ float s_sp[IPX];
    __shared__ float s_ga[NCR], s_gb[NCR];
    __shared__ float s_gac[NC], s_gbc[NC];

    char* sbase;
    { uintptr_t p0 = (uintptr_t)dyn; p0 = (p0 + 1023) & ~(uintptr_t)1023; sbase = (char*)p0; }
    char* sAc = sbase;                                            // [2][ABUF_BYTES]
    unsigned long long* sBb = (unsigned long long*)(sbase + 2*ABUF_BYTES);  // [2][1728]
    uint32_t sB_u32 = smem_u32(sBb);

    int ytile = blockIdx.x, bh = blockIdx.y;
    int b = bh >> 2, h = bh & 3;
    int y0 = ytile * ROWS;
    int tid = threadIdx.x, lane = tid & 31, w = tid >> 5;

    if (tid < NC) bn_affine(tid, gamma, beta, s_gac[tid], s_gbc[tid]);
    for (int i = tid; i < IPX; i += 256) {
        int row = i / 66, col = i - row*66;
        s_sp[i] = d_sp[bh*NHW + (y0 + row)*NH + col];
    }
    __syncthreads();
    for (int i = tid; i < NCR; i += 256) {
        float ca = d_ca[bh*NCR + i];
        int c = i >> 2;
        s_ga[i] = s_gac[c] * ca;
        s_gb[i] = s_gbc[c] * ca;
    }
    __syncthreads();          // <-- RACE FIX: s_ga/s_gb visible before A-build reads

    float acc[4][6][4];
    #pragma unroll
    for (int t = 0; t < 4; t++)
        #pragma unroll
        for (int nt = 0; nt < 6; nt++)
            #pragma unroll
            for (int q = 0; q < 4; q++) acc[t][nt][q] = 0.f;

    // fragment geometry: warp w -> output row w, tiles t = x-quarters 0..3
    int matrix = lane >> 3, mrow = lane & 7;
    int fragrow = ((matrix & 1) << 3) + mrow;
    int colhalf = matrix >> 1;
    uint32_t sA_u32 = smem_u32(sAc);
    uint32_t pxoff[4];
    #pragma unroll
    for (int t = 0; t < 4; t++)
        pxoff[t] = (uint32_t)((w*66 + t*16 + fragrow)*32 + colhalf*16);

    const float* xb = x + (size_t)b * NCR * NHW;
    const uint4* wbsrc = (const uint4*)(d_wb) + (size_t)h * NCHUNK * 864;

    // ---- prologue: B chunk0 via cp.async, build A chunk0 ----
    #pragma unroll
    for (int i = tid; i < 864; i += 256)
        CP_ASYNC16(sB_u32 + (uint32_t)(i*16), (const char*)(wbsrc + i));
    CP_ASYNC_COMMIT();
    for (int s = tid; s < 2*IPX; s += 256) {
        int hh = s / IPX, p = s - hh*IPX;
        int row = p / 66, col = p - row*66;
        const float* xp = xb + (size_t)(hh*8) * NHW + (y0 + row)*NH + col;
        float sp = s_sp[p];
        uint32_t wv[4];
        #pragma unroll
        for (int j = 0; j < 4; j++) {
            int cra = hh*8 + 2*j;
            float v0 = fmaxf(fmaf(s_ga[cra],     xp[(size_t)(2*j)*NHW],     s_gb[cra]),     0.f) * sp;
            float v1 = fmaxf(fmaf(s_ga[cra + 1], xp[(size_t)(2*j + 1)*NHW], s_gb[cra + 1]), 0.f) * sp;
            __half h0 = __float2half(v0), h1 = __float2half(v1);
            wv[j] = (uint32_t)__half_as_ushort(h0) | ((uint32_t)__half_as_ushort(h1) << 16);
        }
        uint32_t off = (uint32_t)(p*32 + hh*16); off ^= (off >> 3) & 0x10;
        *(uint4*)(sAc + off) = make_uint4(wv[0], wv[1], wv[2], wv[3]);
    }
    CP_ASYNC_WAIT0();
    __syncthreads();

    // ---- main pipeline ----
    for (int chunk = 0; chunk < NCHUNK; chunk++) {
        int cb = chunk & 1, nb = cb ^ 1;
        int nk = (chunk + 1 < NCHUNK) ? chunk + 1 : 0;
        int ncr0 = nk * CHC;

        // (1) issue cp.async for next B into other buffer (flies during MMA)
        {
            const uint4* bs = wbsrc + (size_t)nk * 864;
            uint32_t bd = sB_u32 + (uint32_t)(nb * BBUF_BYTES);
            #pragma unroll
            for (int i = tid; i < 864; i += 256)
                CP_ASYNC16(bd + (uint32_t)(i*16), (const char*)(bs + i));
            CP_ASYNC_COMMIT();
        }

        // (2) MMA taps on current buffer: 4 m-tiles per warp
        uint32_t abase = sA_u32 + (uint32_t)cb * ABUF_BYTES;
        const unsigned long long* bcur = sBb + cb*1728 + lane;
        #pragma unroll
        for (int tap = 0; tap < 9; tap++) {
            const int d = (tap/3)*66 + (tap%3);
            uint32_t fa[4][4];
            #pragma unroll
            for (int t = 0; t < 4; t++) {
                uint32_t o = pxoff[t] + (uint32_t)(d*32); o ^= (o >> 3) & 0x10;
                LDSM_X4(fa[t][0], fa[t][1], fa[t][2], fa[t][3], abase + o);
            }
            const unsigned long long* bp = bcur + tap*192;
            #pragma unroll
            for (int nt = 0; nt < 6; nt++) {
                unsigned long long b2 = bp[nt*32];
                uint32_t b0 = (uint32_t)b2, b1 = (uint32_t)(b2 >> 32);
                #pragma unroll
                for (int t = 0; t < 4; t++)
                    MMA16816F16(acc[t][nt], fa[t][0], fa[t][1], fa[t][2], fa[t][3], b0, b1);
            }
        }

        // (3) build next A straight from gmem into other buffer
        for (int s = tid; s < 2*IPX; s += 256) {
            int hh = s / IPX, p = s - hh*IPX;
            int row = p / 66, col = p - row*66;
            const float* xp = xb + (size_t)(ncr0 + hh*8) * NHW + (y0 + row)*NH + col;
            float sp = s_sp[p];
            uint32_t wv[4];
            #pragma unroll
            for (int j = 0; j < 4; j++) {
                int cra = ncr0 + hh*8 + 2*j;
                float v0 = fmaxf(fmaf(s_ga[cra],     xp[(size_t)(2*j)*NHW],     s_gb[cra]),     0.f) * sp;
                float v1 = fmaxf(fmaf(s_ga[cra + 1], xp[(size_t)(2*j + 1)*NHW], s_gb[cra + 1]), 0.f) * sp;
                __half h0 = __float2half(v0), h1 = __float2half(v1);
                wv[j] = (uint32_t)__half_as_ushort(h0) | ((uint32_t)__half_as_ushort(h1) << 16);
            }
            uint32_t off = (uint32_t)(p*32 + hh*16); off ^= (off >> 3) & 0x10;
            *(uint4*)(sAc + (size_t)nb * ABUF_BYTES + off) = make_uint4(wv[0], wv[1], wv[2], wv[3]);
        }
        CP_ASYNC_WAIT0();
        __syncthreads();
    }

    // epilogue: warp w -> output row y0+w
    int oy = y0 + w;
    #pragma unroll
    for (int t = 0; t < 4; t++) {
        int ox = t*16 + (lane >> 2);
        #pragma unroll
        for (int nt = 0; nt < 6; nt++) {
            int o0 = nt*8 + (lane & 3)*2;
            size_t i0 = (((size_t)(b*144 + o0))*4 + h)*4096 + (size_t)oy*64;
            out[i0 + ox]               = acc[t][nt][0];
            out[i0 + 16384 + ox]       = acc[t][nt][1];
            out[i0 + ox + 8]           = acc[t][nt][2];
            out[i0 + 16384 + ox + 8]   = acc[t][nt][3];
        }
    }
}

// ---------------- L4: dense concat crop ----------------
__global__ void k_crop(const float* __restrict__ x, float* __restrict__ out) {
    int idx = blockIdx.x*256 + threadIdx.x;
    if (idx >= NB*NC*NR*64*16) return;
    int q   = idx & 15;
    int y   = (idx >> 4) & 63;
    int brc = idx >> 10;
    int b   = brc / NCR;
    int crr = brc % NCR;
    int c   = crr >> 2, r = crr & 3;
    const float* src = x + (size_t)brc * NHW + (size_t)(y + 1)*NH + (q*4 + 1);
    float4 v = make_float4(src[0], src[1], src[2], src[3]);
    size_t off = (((size_t)b*144 + 48 + c)*4 + r)*4096 + (size_t)y*64 + q*4;
    *(float4*)(out + off) = v;
}

// ---------------- launch ----------------
extern "C" void kernel_launch(void* const* d_in, const int* in_sizes, int n_in,
                              void* d_out, int out_size) {
    const float* x     = (const float*)d_in[0];
    const float* gamma = (const float*)d_in[1];
    const float* beta  = (const float*)d_in[2];
    const float* fc1   = (const float*)d_in[3];
    const float* fc2   = (const float*)d_in[4];
    const float* sa    = (const float*)d_in[5];
    const float* cw    = (const float*)d_in[6];
    float* out = (float*)d_out;
    (void)in_sizes; (void)n_in; (void)out_size;

    static int smem_set = 0;
    if (!smem_set) {
        cudaFuncSetAttribute(k_conv, cudaFuncAttributeMaxDynamicSharedMemorySize, CONV_DYN);
        smem_set = 1;
    }

    int init_blocks = 775 + (WB_TOTAL + 255)/256;
    k_init<<<init_blocks, 256>>>(x, cw, sa);                       // 0
    k_pool<<<NB*NCR + PB*NB*NR, 256>>>(x, gamma, beta);            // 1
    k_att <<<NB + PB*NB*NR, 256>>>(fc1, fc2);                      // 2
    k_conv<<<dim3(8, NB*NR), 256, CONV_DYN>>>(x, gamma, beta, out);   // 3  <- profiled
    k_crop<<<(NB*NC*NR*64*16 + 255)/256, 256>>>(x, out);           // 4
}

// round 15
// speedup vs baseline: 1.3958x; 1.0720x over previous
#include <cuda_runtime.h>
#include <cuda_fp16.h>
#include <math.h>
#include <stdint.h>

#define NB 16
#define NC 96
#define NR 4
#define NO 48
#define NH 66
#define NHW (NH*NH)          // 4356
#define NCR (NC*NR)          // 384
#define BN_EPS 2e-5f
#define NPIX_PER_CH (NB*NR*NHW)

// ---- conv GEMM config ----
#define CHC 16                          // channels per chunk
#define NCHUNK 24                       // 384/16
#define WB_PER_CHUNK (9*6*32)           // 1728 u64
#define WB_TOTAL (NR*NCHUNK*WB_PER_CHUNK)
#define BBUF_BYTES (WB_PER_CHUNK*8)     // 13824
#define ROWS 8                          // output rows per block
#define IR (ROWS+2)                     // 10
#define IPX (IR*66)                     // 660
#define ABUF_BYTES (IPX*32)             // 21120 (fp16, 32B/px)
#define CONV_DYN (1024 + 2*ABUF_BYTES + 2*BBUF_BYTES)   // 70912

// ---------------- scratch (device globals) ----------------
__device__ float d_psum[NC*8];
__device__ float d_psq[NC*8];
__device__ float d_savg[NB*NCR];
__device__ float d_smax[NB*NCR];
__device__ float d_ca[NB*NR*NCR];
__device__ float d_um[NB*NR*NHW];
__device__ float d_ux[NB*NR*NHW];
__device__ float d_sp[NB*NR*NHW];
__device__ float d_wsa[NR*2*NR*49];
__device__ unsigned long long d_wb[WB_TOTAL];
// u = fp16(relu(bn(x))), chunk-major packed: [b][chunk][px][16ch*2B]
__device__ unsigned char d_u[(size_t)NB*NCHUNK*NHW*32];

__device__ __forceinline__ uint32_t smem_u32(const void* p) {
    uint32_t a;
    asm("{ .reg .u64 t; cvta.to.shared.u64 t, %1; cvt.u32.u64 %0, t; }" : "=r"(a) : "l"(p));
    return a;
}
__device__ __forceinline__ float warpSum(float v) {
    #pragma unroll
    for (int o = 16; o; o >>= 1) v += __shfl_down_sync(0xffffffffu, v, o);
    return v;
}
__device__ __forceinline__ float warpMax(float v) {
    #pragma unroll
    for (int o = 16; o; o >>= 1) v = fmaxf(v, __shfl_down_sync(0xffffffffu, v, o));
    return v;
}
__device__ __forceinline__ float sigmoidf(float v) { return 1.f / (1.f + expf(-v)); }

#define LDSM_X4(r0, r1, r2, r3, addr) \
    asm volatile("ldmatrix.sync.aligned.m8n8.x4.shared.b16 {%0,%1,%2,%3}, [%4];" \
        : "=r"(r0), "=r"(r1), "=r"(r2), "=r"(r3) : "r"(addr))

#define MMA16816F16(c, a0, a1, a2, a3, b0, b1) \
    asm volatile("mma.sync.aligned.m16n8k16.row.col.f32.f16.f16.f32 " \
        "{%0,%1,%2,%3}, {%4,%5,%6,%7}, {%8,%9}, {%0,%1,%2,%3};" \
        : "+f"((c)[0]), "+f"((c)[1]), "+f"((c)[2]), "+f"((c)[3]) \
        : "r"(a0), "r"(a1), "r"(a2), "r"(a3), "r"(b0), "r"(b1))

#define CP_ASYNC16(dst, src) \
    asm volatile("cp.async.cg.shared.global [%0], [%1], 16;" :: "r"(dst), "l"(src) : "memory")
#define CP_ASYNC_COMMIT() asm volatile("cp.async.commit_group;" ::: "memory")
#define CP_ASYNC_WAIT0()  asm volatile("cp.async.wait_group 0;" ::: "memory")

__device__ __forceinline__ void bn_affine(int c, const float* gamma, const float* beta,
                                          float& ga, float& gb) {
    float s = 0.f, q = 0.f;
    #pragma unroll
    for (int j = 0; j < 8; j++) { s += d_psum[c*8+j]; q += d_psq[c*8+j]; }
    float mean = s * (1.f / NPIX_PER_CH);
    float var  = q * (1.f / NPIX_PER_CH) - mean*mean;
    ga = gamma[c] * rsqrtf(var + BN_EPS);
    gb = beta[c] - mean * ga;
}

// ---------------- L0: stats + SA weights + fp16 B prepack ----------------
__global__ void k_init(const float* __restrict__ x, const float* __restrict__ cw,
                       const float* __restrict__ sw) {
    int bx = blockIdx.x, tid = threadIdx.x;
    if (bx < 768) {
        int c = bx >> 3, part = bx & 7;
        float s = 0.f, q = 0.f;
        #pragma unroll
        for (int b2 = 0; b2 < 2; b2++) {
            const float4* p4 = (const float4*)(x + (size_t)((part*2 + b2)*NC + c) * (NR*NHW));
            for (int i = tid; i < NR*NHW/4; i += 256) {
                float4 v = p4[i];
                s += v.x + v.y + v.z + v.w;
                q += v.x*v.x + v.y*v.y + v.z*v.z + v.w*v.w;
            }
        }
        __shared__ float rs[8], rq[8];
        int wid = tid >> 5, lane = tid & 31;
        s = warpSum(s); q = warpSum(q);
        if (lane == 0) { rs[wid] = s; rq[wid] = q; }
        __syncthreads();
        if (tid == 0) {
            float S = 0.f, Q = 0.f;
            #pragma unroll
            for (int j = 0; j < 8; j++) { S += rs[j]; Q += rq[j]; }
            d_psum[c*8 + part] = S;
            d_psq [c*8 + part] = Q;
        }
    } else if (bx < 775) {
        int idx = (bx - 768)*256 + tid;
        if (idx >= NR*2*NR*49) return;
        int ij = idx % 49; int t = idx / 49;
        int r  = t & 3;    t >>= 2;
        int p  = t & 1;    int h = t >> 1;
        int i = ij / 7, j = ij % 7;
        int rs = (r - h) & 3;
        int si, sj;
        switch (h) {
            case 0:  si = i;     sj = j;     break;
            case 1:  si = j;     sj = 6 - i; break;
            case 2:  si = 6 - i; sj = 6 - j; break;
            default: si = 6 - j; sj = i;     break;
        }
        d_wsa[idx] = sw[(p*NR + rs)*49 + si*7 + sj];
    } else {
        int idx = (bx - 775)*256 + tid;
        if (idx >= WB_TOTAL) return;
        int lane = idx & 31; int t = idx >> 5;
        int nt   = t % 6;    t /= 6;
        int tap  = t % 9;    t /= 9;
        int chunk = t % NCHUNK;
        int h = t / NCHUNK;
        int n = nt*8 + (lane >> 2);
        int k0 = (lane & 3)*2;
        int i = tap / 3, j = tap % 3, si, sj;
        switch (h) {
            case 0:  si = i;     sj = j;     break;
            case 1:  si = j;     sj = 2 - i; break;
            case 2:  si = 2 - i; sj = 2 - j; break;
            default: si = 2 - j; sj = i;     break;
        }
        unsigned long long pk = 0;
        #pragma unroll
        for (int q = 0; q < 4; q++) {
            int kk = k0 + (q & 1) + (q >> 1)*8;
            int cr = chunk*CHC + kk;
            int c = cr >> 2, r = cr & 3;
            int rs = (r - h) & 3;
            float w = cw[(((n*NC + c)*NR + rs)*3 + si)*3 + sj];
            unsigned short bits = __half_as_ushort(__float2half(w));
            pk |= (unsigned long long)bits << (q*16);
        }
        d_wb[idx] = pk;
    }
}

// ---------------- L1: squeeze+u-precompute (per chunk) + channel pooling ----------
#define PB 18
__global__ void k_pool(const float* __restrict__ x, const float* __restrict__ gamma,
                       const float* __restrict__ beta) {
    int bx = blockIdx.x, tid = threadIdx.x;
    if (bx < NB*NCHUNK) {               // squeeze + write u for one (b, chunk)
        int b = bx / NCHUNK, chunk = bx % NCHUNK;
        int cr0 = chunk * CHC;
        __shared__ float sga[CHC], sgb[CHC];
        __shared__ float rsum[8][CHC], rmax[8][CHC];
        if (tid < CHC) bn_affine((cr0 + tid) >> 2, gamma, beta, sga[tid], sgb[tid]);
        __syncthreads();
        float sums[CHC], maxs[CHC];
        #pragma unroll
        for (int j = 0; j < CHC; j++) { sums[j] = 0.f; maxs[j] = 0.f; }
        const float* xb = x + (size_t)b * NCR * NHW + (size_t)cr0 * NHW;
        unsigned char* ub = d_u + (size_t)(b*NCHUNK + chunk) * NHW * 32;
        for (int p = tid; p < NHW; p += 256) {
            uint32_t wv[8];
            #pragma unroll
            for (int j = 0; j < CHC; j += 2) {
                float v0 = fmaxf(fmaf(sga[j],     xb[(size_t)j*NHW + p],     sgb[j]),     0.f);
                float v1 = fmaxf(fmaf(sga[j + 1], xb[(size_t)(j+1)*NHW + p], sgb[j + 1]), 0.f);
                sums[j] += v0; maxs[j] = fmaxf(maxs[j], v0);
                sums[j+1] += v1; maxs[j+1] = fmaxf(maxs[j+1], v1);
                wv[j >> 1] = (uint32_t)__half_as_ushort(__float2half(v0))
                           | ((uint32_t)__half_as_ushort(__float2half(v1)) << 16);
            }
            *(uint4*)(ub + (size_t)p*32)      = make_uint4(wv[0], wv[1], wv[2], wv[3]);
            *(uint4*)(ub + (size_t)p*32 + 16) = make_uint4(wv[4], wv[5], wv[6], wv[7]);
        }
        int wid = tid >> 5, lane = tid & 31;
        #pragma unroll
        for (int j = 0; j < CHC; j++) {
            float s = warpSum(sums[j]);
            float m = warpMax(maxs[j]);
            if (lane == 0) { rsum[wid][j] = s; rmax[wid][j] = m; }
        }
        __syncthreads();
        if (tid < CHC) {
            float S = 0.f, M = 0.f;
            #pragma unroll
            for (int k = 0; k < 8; k++) { S += rsum[k][tid]; M = fmaxf(M, rmax[k][tid]); }
            d_savg[b*NCR + cr0 + tid] = S * (1.f / NHW);
            d_smax[b*NCR + cr0 + tid] = M;
        }
    } else {                             // channel pooling per (b,r,pixel-block)
        __shared__ float sga[NC], sgb[NC];
        if (tid < NC) bn_affine(tid, gamma, beta, sga[tid], sgb[tid]);
        __syncthreads();
        int idx = bx - NB*NCHUNK;
        int pb = idx % PB, br = idx / PB;
        int b = br >> 2, r = br & 3;
        int p = pb*256 + tid;
        if (p >= NHW) return;
        float s = 0.f, m = 0.f;
        const float* xb = x + (size_t)(b*NCR + r) * NHW + p;
        #pragma unroll 4
        for (int c = 0; c < NC; c++) {
            float v = fmaxf(fmaf(sga[c], xb[(size_t)(c*4) * NHW], sgb[c]), 0.f);
            s += v; m = fmaxf(m, v);
        }
        d_um[br*NHW + p] = s * (1.f / NC);
        d_ux[br*NHW + p] = m;
    }
}

// ---------------- L2: merged channel-attention MLP + spatial attention ------------
__global__ void k_att(const float* __restrict__ fc1, const float* __restrict__ fc2) {
    int bx = blockIdx.x, tid = threadIdx.x;
    if (bx < NB) {
        int b = bx;
        __shared__ float sA[NCR], sM[NCR], f1[2*NCR], f2[NC*8];
        __shared__ float dred[16], hsum[8];
        for (int i = tid; i < NCR; i += 256) { sA[i] = d_savg[b*NCR + i]; sM[i] = d_smax[b*NCR + i]; }
        for (int i = tid; i < 2*NCR; i += 256) { f1[i] = fc1[i]; f2[i] = fc2[i]; }
        __syncthreads();
        int wid = tid >> 5, lane = tid & 31;
        #pragma unroll
        for (int dd = 0; dd < 2; dd++) {
            int d = wid*2 + dd;
            int sel = d & 1, he = d >> 1;
            int h = he >> 1, e = he & 1;
            const float* sv = sel ? sM : sA;
            float sum = 0.f;
            for (int k = lane; k < NCR; k += 32) {
                int r = k & 3;
                sum += sv[k] * f1[e*NCR + (k & ~3) + (((r - h) & 3))];
            }
            sum = warpSum(sum);
            if (lane == 0) dred[d] = fmaxf(sum, 0.f);
        }
        __syncthreads();
        if (tid < 8) hsum[tid] = dred[tid*2] + dred[tid*2 + 1];
        __syncthreads();
        for (int idx = tid; idx < NR*NCR; idx += 256) {
            int h = idx / NCR, cr = idx % NCR;
            int c = cr >> 2, r = cr & 3;
            int rs = (r - h) & 3;
            float v = hsum[h*2 + 0] * f2[c*8 + rs]
                    + hsum[h*2 + 1] * f2[c*8 + 4 + rs];
            d_ca[b*(NR*NCR) + idx] = sigmoidf(v);
        }
    } else {
        __shared__ float ws[2*NR*49];
        int idx = bx - NB;
        int pb = idx % PB, bh = idx / PB;
        int b = bh >> 2, h = bh & 3;
        for (int i = tid; i < 2*NR*49; i += 256) ws[i] = d_wsa[h*(2*NR*49) + i];
        __syncthreads();
        int p = pb*256 + tid;
        if (p >= NHW) return;
        int y = p / NH, x0 = p % NH;
        float s = 0.f;
        #pragma unroll
        for (int p2 = 0; p2 < 2; p2++) {
            const float* ubase = p2 ? d_ux : d_um;
            #pragma unroll
            for (int r = 0; r < NR; r++) {
                const float* u = ubase + (size_t)(b*4 + r) * NHW;
                const float* w = ws + (p2*4 + r)*49;
                #pragma unroll
                for (int i = 0; i < 7; i++) {
                    int Y = y + i - 3;
                    if (Y < 0 || Y >= NH) continue;
                    #pragma unroll
                    for (int j = 0; j < 7; j++) {
                        int X = x0 + j - 3;
                        if (X < 0 || X >= NH) continue;
                        s += u[Y*NH + X] * w[i*7 + j];
                    }
                }
            }
        }
        d_sp[bh*NHW + p] = sigmoidf(s);
    }
}

// ---------------- L3 (PROFILED): fp16 HMMA conv, u-precomputed A-build ------------
// Block: 256 thr = 8 warps; 8 output rows x 64 px (M=512); warp w -> output row w.
// A-build: LDG.128 of prepacked fp16 u + half2 gate (ca x sp) + swizzled STS.128.
__global__ __launch_bounds__(256, 2) void k_conv(float* __restrict__ out) {
    extern __shared__ __align__(16) char dyn[];
    __shared__ float s_sp[IPX];
    __shared__ __half2 s_cah[NCR/2];

    char* sbase;
    { uintptr_t p0 = (uintptr_t)dyn; p0 = (p0 + 1023) & ~(uintptr_t)1023; sbase = (char*)p0; }
    char* sAc = sbase;                                            // [2][ABUF_BYTES]
    unsigned long long* sBb = (unsigned long long*)(sbase + 2*ABUF_BYTES);  // [2][1728]
    uint32_t sB_u32 = smem_u32(sBb);

    int ytile = blockIdx.x, bh = blockIdx.y;
    int b = bh >> 2, h = bh & 3;
    int y0 = ytile * ROWS;
    int tid = threadIdx.x, lane = tid & 31, w = tid >> 5;

    for (int i = tid; i < IPX; i += 256) {
        int row = i / 66, col = i - row*66;
        s_sp[i] = d_sp[bh*NHW + (y0 + row)*NH + col];
    }
    for (int i = tid; i < NCR/2; i += 256) {
        s_cah[i] = __floats2half2_rn(d_ca[bh*NCR + 2*i], d_ca[bh*NCR + 2*i + 1]);
    }
    __syncthreads();          // s_sp/s_cah visible before any A-build reads

    float acc[4][6][4];
    #pragma unroll
    for (int t = 0; t < 4; t++)
        #pragma unroll
        for (int nt = 0; nt < 6; nt++)
            #pragma unroll
            for (int q = 0; q < 4; q++) acc[t][nt][q] = 0.f;

    // fragment geometry: warp w -> output row w, tiles t = x-quarters 0..3
    int matrix = lane >> 3, mrow = lane & 7;
    int fragrow = ((matrix & 1) << 3) + mrow;
    int colhalf = matrix >> 1;
    uint32_t sA_u32 = smem_u32(sAc);
    uint32_t pxoff[4];
    #pragma unroll
    for (int t = 0; t < 4; t++)
        pxoff[t] = (uint32_t)((w*66 + t*16 + fragrow)*32 + colhalf*16);

    const unsigned char* ub = d_u + (size_t)(b*NCHUNK) * NHW * 32;
    const uint4* wbsrc = (const uint4*)(d_wb) + (size_t)h * NCHUNK * 864;

    // ---- prologue: B chunk0 via cp.async, build A chunk0 ----
    #pragma unroll
    for (int i = tid; i < 864; i += 256)
        CP_ASYNC16(sB_u32 + (uint32_t)(i*16), (const char*)(wbsrc + i));
    CP_ASYNC_COMMIT();
    #pragma unroll 2
    for (int s = tid; s < 2*IPX; s += 256) {
        int hh = s / IPX, p = s - hh*IPX;
        int row = p / 66, col = p - row*66;
        int q = (y0 + row)*NH + col;
        uint4 yv = *(const uint4*)(ub + (size_t)q*32 + hh*16);
        __half2 sp2 = __float2half2_rn(s_sp[p]);
        const __half2* cah = s_cah + hh*4;
        uint32_t wv[4];
        #pragma unroll
        for (int j = 0; j < 4; j++) {
            __half2 y2 = *((__half2*)&yv + j);
            __half2 v2 = __hmul2(__hmul2(y2, cah[j]), sp2);
            wv[j] = *(uint32_t*)&v2;
        }
        uint32_t off = (uint32_t)(p*32 + hh*16); off ^= (off >> 3) & 0x10;
        *(uint4*)(sAc + off) = make_uint4(wv[0], wv[1], wv[2], wv[3]);
    }
    CP_ASYNC_WAIT0();
    __syncthreads();

    // ---- main pipeline ----
    for (int chunk = 0; chunk < NCHUNK; chunk++) {
        int cb = chunk & 1, nb = cb ^ 1;
        int nk = (chunk + 1 < NCHUNK) ? chunk + 1 : 0;

        // (1) issue cp.async for next B into other buffer (flies during MMA)
        {
            const uint4* bs = wbsrc + (size_t)nk * 864;
            uint32_t bd = sB_u32 + (uint32_t)(nb * BBUF_BYTES);
            #pragma unroll
            for (int i = tid; i < 864; i += 256)
                CP_ASYNC16(bd + (uint32_t)(i*16), (const char*)(bs + i));
            CP_ASYNC_COMMIT();
        }

        // (2) MMA taps on current buffer: 4 m-tiles per warp
        uint32_t abase = sA_u32 + (uint32_t)cb * ABUF_BYTES;
        const unsigned long long* bcur = sBb + cb*1728 + lane;
        #pragma unroll
        for (int tap = 0; tap < 9; tap++) {
            const int d = (tap/3)*66 + (tap%3);
            uint32_t fa[4][4];
            #pragma unroll
            for (int t = 0; t < 4; t++) {
                uint32_t o = pxoff[t] + (uint32_t)(d*32); o ^= (o >> 3) & 0x10;
                LDSM_X4(fa[t][0], fa[t][1], fa[t][2], fa[t][3], abase + o);
            }
            const unsigned long long* bp = bcur + tap*192;
            #pragma unroll
            for (int nt = 0; nt < 6; nt++) {
                unsigned long long b2 = bp[nt*32];
                uint32_t b0 = (uint32_t)b2, b1 = (uint32_t)(b2 >> 32);
                #pragma unroll
                for (int t = 0; t < 4; t++)
                    MMA16816F16(acc[t][nt], fa[t][0], fa[t][1], fa[t][2], fa[t][3], b0, b1);
            }
        }

        // (3) build next A from prepacked u into other buffer
        {
            const unsigned char* ubn = ub + (size_t)nk * NHW * 32;
            char* dst = sAc + (size_t)nb * ABUF_BYTES;
            #pragma unroll 2
            for (int s = tid; s < 2*IPX; s += 256) {
                int hh = s / IPX, p = s - hh*IPX;
                int row = p / 66, col = p - row*66;
                int q = (y0 + row)*NH + col;
                uint4 yv = *(const uint4*)(ubn + (size_t)q*32 + hh*16);
                __half2 sp2 = __float2half2_rn(s_sp[p]);
                const __half2* cah = s_cah + nk*8 + hh*4;
                uint32_t wv[4];
                #pragma unroll
                for (int j = 0; j < 4; j++) {
                    __half2 y2 = *((__half2*)&yv + j);
                    __half2 v2 = __hmul2(__hmul2(y2, cah[j]), sp2);
                    wv[j] = *(uint32_t*)&v2;
                }
                uint32_t off = (uint32_t)(p*32 + hh*16); off ^= (off >> 3) & 0x10;
                *(uint4*)(dst + off) = make_uint4(wv[0], wv[1], wv[2], wv[3]);
            }
        }
        CP_ASYNC_WAIT0();
        __syncthreads();
    }

    // epilogue: warp w -> output row y0+w
    int oy = y0 + w;
    #pragma unroll
    for (int t = 0; t < 4; t++) {
        int ox = t*16 + (lane >> 2);
        #pragma unroll
        for (int nt = 0; nt < 6; nt++) {
            int o0 = nt*8 + (lane & 3)*2;
            size_t i0 = (((size_t)(b*144 + o0))*4 + h)*4096 + (size_t)oy*64;
            out[i0 + ox]               = acc[t][nt][0];
            out[i0 + 16384 + ox]       = acc[t][nt][1];
            out[i0 + ox + 8]           = acc[t][nt][2];
            out[i0 + 16384 + ox + 8]   = acc[t][nt][3];
        }
    }
}

// ---------------- L4: dense concat crop ----------------
__global__ void k_crop(const float* __restrict__ x, float* __restrict__ out) {
    int idx = blockIdx.x*256 + threadIdx.x;
    if (idx >= NB*NC*NR*64*16) return;
    int q   = idx & 15;
    int y   = (idx >> 4) & 63;
    int brc = idx >> 10;
    int b   = brc / NCR;
    int crr = brc % NCR;
    int c   = crr >> 2, r = crr & 3;
    const float* src = x + (size_t)brc * NHW + (size_t)(y + 1)*NH + (q*4 + 1);
    float4 v = make_float4(src[0], src[1], src[2], src[3]);
    size_t off = (((size_t)b*144 + 48 + c)*4 + r)*4096 + (size_t)y*64 + q*4;
    *(float4*)(out + off) = v;
}

// ---------------- launch ----------------
extern "C" void kernel_launch(void* const* d_in, const int* in_sizes, int n_in,
                              void* d_out, int out_size) {
    const float* x     = (const float*)d_in[0];
    const float* gamma = (const float*)d_in[1];
    const float* beta  = (const float*)d_in[2];
    const float* fc1   = (const float*)d_in[3];
    const float* fc2   = (const float*)d_in[4];
    const float* sa    = (const float*)d_in[5];
    const float* cw    = (const float*)d_in[6];
    float* out = (float*)d_out;
    (void)in_sizes; (void)n_in; (void)out_size;

    static int smem_set = 0;
    if (!smem_set) {
        cudaFuncSetAttribute(k_conv, cudaFuncAttributeMaxDynamicSharedMemorySize, CONV_DYN);
        smem_set = 1;
    }

    int init_blocks = 775 + (WB_TOTAL + 255)/256;
    k_init<<<init_blocks, 256>>>(x, cw, sa);                       // 0
    k_pool<<<NB*NCHUNK + PB*NB*NR, 256>>>(x, gamma, beta);         // 1
    k_att <<<NB + PB*NB*NR, 256>>>(fc1, fc2);                      // 2
    k_conv<<<dim3(8, NB*NR), 256, CONV_DYN>>>(out);                // 3  <- profiled
    k_crop<<<(NB*NC*NR*64*16 + 255)/256, 256>>>(x, out);           // 4
}